// round 15
// baseline (speedup 1.0000x reference)
#include <cuda_runtime.h>
#include <cuda_fp16.h>

#define NN 100000
#define EE 3200000
#define GG 1024
#define DD 32
#define STRIDE 80   // padded CSR row stride; max degree ~57 (8.5 sigma), safe

// ---- scratch (static __device__, no allocations) ----
__device__ int    g_cnt[NN];
__device__ int    g_csr[NN * STRIDE];
__device__ float4 g_x4[NN];
__device__ __half g_hh0[NN * DD];   // layer1 out (gathered by layer2) - 64B rows
__device__ __half g_hh1[NN * DD];   // layer2 out (gathered by layer3)
__device__ float4 g_aggx[NN];       // layer1 aggregated x
__device__ float  g_agg[NN * DD];   // layers 2/3 aggregated rows (fp32)
__device__ float  g_pool[GG * DD];

// ---------------- init: zero cnt + pool, pad x to float4 ----------------
__global__ void k_init(const float* __restrict__ x) {
    int i = blockIdx.x * blockDim.x + threadIdx.x;
    if (i < NN) {
        g_cnt[i] = 0;
        g_x4[i] = make_float4(x[3 * i], x[3 * i + 1], x[3 * i + 2], 0.f);
    }
    if (i < GG * DD) g_pool[i] = 0.f;
}

// ---------------- one-pass padded CSR build, 8 edges/thread ----------------
__global__ void k_fill(const int* __restrict__ ei) {
    int e = (blockIdx.x * blockDim.x + threadIdx.x) * 8;
    if (e < EE) {
        int4 s0 = *(const int4*)(ei + e);
        int4 s1 = *(const int4*)(ei + e + 4);
        int4 d0 = *(const int4*)(ei + EE + e);
        int4 d1 = *(const int4*)(ei + EE + e + 4);
        int p0 = atomicAdd(&g_cnt[d0.x], 1);
        int p1 = atomicAdd(&g_cnt[d0.y], 1);
        int p2 = atomicAdd(&g_cnt[d0.z], 1);
        int p3 = atomicAdd(&g_cnt[d0.w], 1);
        int p4 = atomicAdd(&g_cnt[d1.x], 1);
        int p5 = atomicAdd(&g_cnt[d1.y], 1);
        int p6 = atomicAdd(&g_cnt[d1.z], 1);
        int p7 = atomicAdd(&g_cnt[d1.w], 1);
        if (p0 < STRIDE) g_csr[d0.x * STRIDE + p0] = s0.x;
        if (p1 < STRIDE) g_csr[d0.y * STRIDE + p1] = s0.y;
        if (p2 < STRIDE) g_csr[d0.z * STRIDE + p2] = s0.z;
        if (p3 < STRIDE) g_csr[d0.w * STRIDE + p3] = s0.w;
        if (p4 < STRIDE) g_csr[d1.x * STRIDE + p4] = s1.x;
        if (p5 < STRIDE) g_csr[d1.y * STRIDE + p5] = s1.y;
        if (p6 < STRIDE) g_csr[d1.z * STRIDE + p6] = s1.z;
        if (p7 < STRIDE) g_csr[d1.w * STRIDE + p7] = s1.w;
    }
}

// ---------------- layer-1 aggregation: x gather ----------------
__global__ void k_agg1() {
    int warp = (blockIdx.x * blockDim.x + threadIdx.x) >> 5;
    int lane = threadIdx.x & 31;
    if (warp >= NN) return;
    int n = warp;
    int o = n * STRIDE;
    int d = min(g_cnt[n], STRIDE);
    float p0 = 0.f, p1 = 0.f, p2 = 0.f;
    for (int j = lane; j < d; j += 32) {
        float4 r = g_x4[g_csr[o + j]];
        p0 += r.x; p1 += r.y; p2 += r.z;
    }
#pragma unroll
    for (int w = 16; w > 0; w >>= 1) {
        p0 += __shfl_xor_sync(0xffffffffu, p0, w);
        p1 += __shfl_xor_sync(0xffffffffu, p1, w);
        p2 += __shfl_xor_sync(0xffffffffu, p2, w);
    }
    if (lane == 0) {
        float4 s = g_x4[n];
        g_aggx[n] = make_float4(p0 + s.x, p1 + s.y, p2 + s.z, 0.f);
    }
}

// 4-way matmul macro: ACC[q] += stage[q] . W
#define MM4(ACC, W, SBASE)                                               \
    _Pragma("unroll")                                                    \
    for (int kk = 0; kk < 8; kk++) {                                     \
        float4 v0 = *(const float4*)&(SBASE)[0 * 32 + kk * 4];           \
        float4 v1 = *(const float4*)&(SBASE)[1 * 32 + kk * 4];           \
        float4 v2 = *(const float4*)&(SBASE)[2 * 32 + kk * 4];           \
        float4 v3 = *(const float4*)&(SBASE)[3 * 32 + kk * 4];           \
        ACC[0] = fmaf(v0.x, W[4 * kk + 0], ACC[0]);                      \
        ACC[1] = fmaf(v1.x, W[4 * kk + 0], ACC[1]);                      \
        ACC[2] = fmaf(v2.x, W[4 * kk + 0], ACC[2]);                      \
        ACC[3] = fmaf(v3.x, W[4 * kk + 0], ACC[3]);                      \
        ACC[0] = fmaf(v0.y, W[4 * kk + 1], ACC[0]);                      \
        ACC[1] = fmaf(v1.y, W[4 * kk + 1], ACC[1]);                      \
        ACC[2] = fmaf(v2.y, W[4 * kk + 1], ACC[2]);                      \
        ACC[3] = fmaf(v3.y, W[4 * kk + 1], ACC[3]);                      \
        ACC[0] = fmaf(v0.z, W[4 * kk + 2], ACC[0]);                      \
        ACC[1] = fmaf(v1.z, W[4 * kk + 2], ACC[1]);                      \
        ACC[2] = fmaf(v2.z, W[4 * kk + 2], ACC[2]);                      \
        ACC[3] = fmaf(v3.z, W[4 * kk + 2], ACC[3]);                      \
        ACC[0] = fmaf(v0.w, W[4 * kk + 3], ACC[0]);                      \
        ACC[1] = fmaf(v1.w, W[4 * kk + 3], ACC[1]);                      \
        ACC[2] = fmaf(v2.w, W[4 * kk + 3], ACC[2]);                      \
        ACC[3] = fmaf(v3.w, W[4 * kk + 3], ACC[3]);                      \
    }

// ---------------- layer-1 MLP (3 -> 32), quad + prefetch pipeline, writes fp16 ----------------
__global__ void __launch_bounds__(256) k_mlp1(
        const float* __restrict__ Wa, const float* __restrict__ ba,
        const float* __restrict__ Wb, const float* __restrict__ bb,
        const float* __restrict__ gm, const float* __restrict__ be,
        const float* __restrict__ mm, const float* __restrict__ vv) {
    __shared__ float sstage[8][128];
    int lane = threadIdx.x & 31;
    int wi = threadIdx.x >> 5;
    float wa0 = Wa[lane], wa1 = Wa[32 + lane], wa2 = Wa[64 + lane];
    float wb[32];
#pragma unroll
    for (int k = 0; k < 32; k++) wb[k] = Wb[k * 32 + lane];
    float bal = ba[lane], bbl = bb[lane];
    float sc = gm[lane] * rsqrtf(vv[lane] + 1e-5f);
    float sh = be[lane] - mm[lane] * sc;
    int gw = (blockIdx.x * blockDim.x + threadIdx.x) >> 5;
    int nwarps = (gridDim.x * blockDim.x) >> 5;
    float* st = sstage[wi];
    const int NQ = NN / 4;
    if (gw >= NQ) return;
    float4 a0 = g_aggx[4 * gw], a1 = g_aggx[4 * gw + 1];
    float4 a2 = g_aggx[4 * gw + 2], a3 = g_aggx[4 * gw + 3];
    for (int q = gw; q < NQ; q += nwarps) {
        int n0 = 4 * q;
        // first matmul (3->32) straight from registers
        float c0 = fmaf(a0.x, wa0, bal), c1 = fmaf(a1.x, wa0, bal);
        float c2 = fmaf(a2.x, wa0, bal), c3 = fmaf(a3.x, wa0, bal);
        c0 = fmaf(a0.y, wa1, c0); c1 = fmaf(a1.y, wa1, c1);
        c2 = fmaf(a2.y, wa1, c2); c3 = fmaf(a3.y, wa1, c3);
        c0 = fmaf(a0.z, wa2, c0); c1 = fmaf(a1.z, wa2, c1);
        c2 = fmaf(a2.z, wa2, c2); c3 = fmaf(a3.z, wa2, c3);
        __syncwarp();
        st[lane] = fmaxf(c0, 0.f);
        st[32 + lane] = fmaxf(c1, 0.f);
        st[64 + lane] = fmaxf(c2, 0.f);
        st[96 + lane] = fmaxf(c3, 0.f);
        __syncwarp();
        // prefetch next quad while MM4 runs
        int qn = q + nwarps;
        if (qn < NQ) {
            a0 = g_aggx[4 * qn];     a1 = g_aggx[4 * qn + 1];
            a2 = g_aggx[4 * qn + 2]; a3 = g_aggx[4 * qn + 3];
        }
        float acc2[4] = {bbl, bbl, bbl, bbl};
        MM4(acc2, wb, st);
#pragma unroll
        for (int u = 0; u < 4; u++)
            g_hh0[(n0 + u) * 32 + lane] =
                __float2half_rn(fmaf(fmaxf(acc2[u], 0.f), sc, sh));
    }
}

// ---------------- fp16 aggregation: 64B rows, 8 edges/warp-iter ----------------
// src==0: g_hh0 ; src==1: g_hh1.  Writes fp32 g_agg.
__global__ void k_aggh(int src) {
    const uint4* __restrict__ hin = (const uint4*)(src ? g_hh1 : g_hh0); // 4 chunks/row
    int warp = (blockIdx.x * blockDim.x + threadIdx.x) >> 5;
    int lane = threadIdx.x & 31;
    if (warp >= NN) return;
    int n = warp;
    int chk = lane & 3;      // 16B chunk (8 halves) 0..3
    int grp = lane >> 2;     // edge group 0..7
    float a0 = 0.f, a1 = 0.f, a2 = 0.f, a3 = 0.f, a4 = 0.f, a5 = 0.f, a6 = 0.f, a7 = 0.f;
    if (grp == 0) {          // self term once
        uint4 v = hin[n * 4 + chk];
        float2 f;
        f = __half22float2(*(__half2*)&v.x); a0 += f.x; a1 += f.y;
        f = __half22float2(*((__half2*)&v.x + 1)); a2 += f.x; a3 += f.y;
        f = __half22float2(*(__half2*)&v.z); a4 += f.x; a5 += f.y;
        f = __half22float2(*((__half2*)&v.z + 1)); a6 += f.x; a7 += f.y;
    }
    int o = n * STRIDE;
    int jend = o + min(g_cnt[n], STRIDE);
#pragma unroll 4
    for (int j = o + grp; j < jend; j += 8) {
        int ss = g_csr[j];               // 8 ints/warp, 4-way broadcast
        uint4 v = hin[ss * 4 + chk];     // 8 distinct 64B rows per warp-iter
        float2 f;
        f = __half22float2(*(__half2*)&v.x); a0 += f.x; a1 += f.y;
        f = __half22float2(*((__half2*)&v.x + 1)); a2 += f.x; a3 += f.y;
        f = __half22float2(*(__half2*)&v.z); a4 += f.x; a5 += f.y;
        f = __half22float2(*((__half2*)&v.z + 1)); a6 += f.x; a7 += f.y;
    }
#pragma unroll
    for (int w = 4; w <= 16; w <<= 1) {
        a0 += __shfl_xor_sync(0xffffffffu, a0, w);
        a1 += __shfl_xor_sync(0xffffffffu, a1, w);
        a2 += __shfl_xor_sync(0xffffffffu, a2, w);
        a3 += __shfl_xor_sync(0xffffffffu, a3, w);
        a4 += __shfl_xor_sync(0xffffffffu, a4, w);
        a5 += __shfl_xor_sync(0xffffffffu, a5, w);
        a6 += __shfl_xor_sync(0xffffffffu, a6, w);
        a7 += __shfl_xor_sync(0xffffffffu, a7, w);
    }
    if (grp == 0) {
        float4* dst = (float4*)g_agg;
        dst[n * 8 + chk * 2]     = make_float4(a0, a1, a2, a3);
        dst[n * 8 + chk * 2 + 1] = make_float4(a4, a5, a6, a7);
    }
}

// ---------------- layer-2 MLP, quad + prefetch pipeline, writes fp16 ----------------
__global__ void __launch_bounds__(256) k_mlp2(
        const float* __restrict__ Wa, const float* __restrict__ ba,
        const float* __restrict__ Wb, const float* __restrict__ bb,
        const float* __restrict__ gm, const float* __restrict__ be,
        const float* __restrict__ mm, const float* __restrict__ vv) {
    __shared__ float sstage[8][128];
    int lane = threadIdx.x & 31;
    int wi = threadIdx.x >> 5;
    float wa[32], wb[32];
#pragma unroll
    for (int k = 0; k < 32; k++) {
        wa[k] = Wa[k * 32 + lane];
        wb[k] = Wb[k * 32 + lane];
    }
    float bal = ba[lane], bbl = bb[lane];
    float sc = gm[lane] * rsqrtf(vv[lane] + 1e-5f);
    float sh = be[lane] - mm[lane] * sc;
    int gw = (blockIdx.x * blockDim.x + threadIdx.x) >> 5;
    int nwarps = (gridDim.x * blockDim.x) >> 5;
    float* st = sstage[wi];
    const int NQ = NN / 4;
    if (gw >= NQ) return;
    float a0 = g_agg[(4 * gw) * 32 + lane];
    float a1 = g_agg[(4 * gw + 1) * 32 + lane];
    float a2 = g_agg[(4 * gw + 2) * 32 + lane];
    float a3 = g_agg[(4 * gw + 3) * 32 + lane];
    for (int q = gw; q < NQ; q += nwarps) {
        int n0 = 4 * q;
        __syncwarp();
        st[lane] = a0; st[32 + lane] = a1; st[64 + lane] = a2; st[96 + lane] = a3;
        __syncwarp();
        // prefetch next quad while the two MM4s run
        int qn = q + nwarps;
        if (qn < NQ) {
            a0 = g_agg[(4 * qn) * 32 + lane];
            a1 = g_agg[(4 * qn + 1) * 32 + lane];
            a2 = g_agg[(4 * qn + 2) * 32 + lane];
            a3 = g_agg[(4 * qn + 3) * 32 + lane];
        }
        float acc[4] = {bal, bal, bal, bal};
        MM4(acc, wa, st);
        __syncwarp();
        st[lane] = fmaxf(acc[0], 0.f);
        st[32 + lane] = fmaxf(acc[1], 0.f);
        st[64 + lane] = fmaxf(acc[2], 0.f);
        st[96 + lane] = fmaxf(acc[3], 0.f);
        __syncwarp();
        float acc2[4] = {bbl, bbl, bbl, bbl};
        MM4(acc2, wb, st);
#pragma unroll
        for (int u = 0; u < 4; u++)
            g_hh1[(n0 + u) * 32 + lane] =
                __float2half_rn(fmaf(fmaxf(acc2[u], 0.f), sc, sh));
    }
}

// ---------------- layer-3 MLP + fused run-length pool, quad + prefetch ----------------
__global__ void __launch_bounds__(256) k_mlp3pool(
        const int* __restrict__ batch,
        const float* __restrict__ Wa, const float* __restrict__ ba,
        const float* __restrict__ Wb, const float* __restrict__ bb,
        const float* __restrict__ gm, const float* __restrict__ be,
        const float* __restrict__ mm, const float* __restrict__ vv) {
    __shared__ float sstage[8][128];
    int lane = threadIdx.x & 31;
    int wi = threadIdx.x >> 5;
    float wa[32], wb[32];
#pragma unroll
    for (int k = 0; k < 32; k++) {
        wa[k] = Wa[k * 32 + lane];
        wb[k] = Wb[k * 32 + lane];
    }
    float bal = ba[lane], bbl = bb[lane];
    float sc = gm[lane] * rsqrtf(vv[lane] + 1e-5f);
    float sh = be[lane] - mm[lane] * sc;
    int gw = (blockIdx.x * blockDim.x + threadIdx.x) >> 5;
    int base = gw * 32;
    if (base >= NN) return;
    float* st = sstage[wi];
    float pacc = 0.f;
    int curb = batch[base];
    float a0 = g_agg[base * 32 + lane];
    float a1 = g_agg[(base + 1) * 32 + lane];
    float a2 = g_agg[(base + 2) * 32 + lane];
    float a3 = g_agg[(base + 3) * 32 + lane];
#pragma unroll 1
    for (int m = 0; m < 8; m++) {
        int n0 = base + 4 * m;
        __syncwarp();
        st[lane] = a0; st[32 + lane] = a1; st[64 + lane] = a2; st[96 + lane] = a3;
        __syncwarp();
        if (m < 7) {
            int nn = n0 + 4;
            a0 = g_agg[nn * 32 + lane];
            a1 = g_agg[(nn + 1) * 32 + lane];
            a2 = g_agg[(nn + 2) * 32 + lane];
            a3 = g_agg[(nn + 3) * 32 + lane];
        }
        float acc[4] = {bal, bal, bal, bal};
        MM4(acc, wa, st);
        __syncwarp();
        st[lane] = fmaxf(acc[0], 0.f);
        st[32 + lane] = fmaxf(acc[1], 0.f);
        st[64 + lane] = fmaxf(acc[2], 0.f);
        st[96 + lane] = fmaxf(acc[3], 0.f);
        __syncwarp();
        float acc2[4] = {bbl, bbl, bbl, bbl};
        MM4(acc2, wb, st);
#pragma unroll
        for (int u = 0; u < 4; u++) {
            float r = fmaf(fmaxf(acc2[u], 0.f), sc, sh);
            int b = batch[n0 + u];
            if (b != curb) {
                atomicAdd(&g_pool[curb * 32 + lane], pacc);
                pacc = 0.f; curb = b;
            }
            pacc += r;
        }
    }
    atomicAdd(&g_pool[curb * 32 + lane], pacc);
}

// ---------------- head MLP ----------------
__global__ void k_final(const float* __restrict__ Wf1, const float* __restrict__ bf1,
                        const float* __restrict__ Wf2, const float* __restrict__ bf2,
                        float* __restrict__ out) {
    __shared__ float sW1[1024], sb1[32], sW2[32];
    int tid = threadIdx.x;
    for (int i = tid; i < 1024; i += blockDim.x) sW1[i] = Wf1[i];
    if (tid < 32) {
        sb1[tid] = bf1[tid];
        sW2[tid] = Wf2[tid];
    }
    __syncthreads();
    int warp = (blockIdx.x * blockDim.x + tid) >> 5;
    int lane = tid & 31;
    if (warp >= GG) return;
    float p = g_pool[warp * 32 + lane];
    float acc = sb1[lane];
#pragma unroll
    for (int k = 0; k < 32; k++) {
        float a = __shfl_sync(0xffffffffu, p, k);
        acc = fmaf(a, sW1[k * 32 + lane], acc);
    }
    acc = fmaxf(acc, 0.f);
    float part = acc * sW2[lane];
#pragma unroll
    for (int w = 16; w > 0; w >>= 1) part += __shfl_xor_sync(0xffffffffu, part, w);
    if (lane == 0) out[warp] = tanhf(part + bf2[0]);
}

extern "C" void kernel_launch(void* const* d_in, const int* in_sizes, int n_in,
                              void* d_out, int out_size) {
    const float* x = (const float*)d_in[0];
    const int* ei = (const int*)d_in[1];
    const int* batch = (const int*)d_in[2];
    const float* P[28];
    for (int i = 0; i < 28; i++) P[i] = (const float*)d_in[3 + i];
    float* out = (float*)d_out;

    const int TB = 256;
    const int node_grid = (NN * 32 + TB - 1) / TB;  // warp per node
    const int mlp_grid = 592;                       // grid-stride quads
    const int pool_grid = (NN + TB - 1) / TB;       // warp per 32 nodes

    k_init<<<(NN + TB - 1) / TB, TB>>>(x);
    k_fill<<<(EE / 8 + TB - 1) / TB, TB>>>(ei);

    // layer 1: x -> aggx -> hh0 (fp16)
    k_agg1<<<node_grid, TB>>>();
    k_mlp1<<<mlp_grid, TB>>>(P[0], P[1], P[2], P[3], P[4], P[5], P[6], P[7]);
    // layer 2: hh0 -> agg -> hh1 (fp16)
    k_aggh<<<node_grid, TB>>>(0);
    k_mlp2<<<mlp_grid, TB>>>(P[8], P[9], P[10], P[11], P[12], P[13], P[14], P[15]);
    // layer 3: hh1 -> agg -> MLP+pool (fused, run-length)
    k_aggh<<<node_grid, TB>>>(1);
    k_mlp3pool<<<pool_grid, TB>>>(batch, P[16], P[17], P[18], P[19], P[20], P[21], P[22], P[23]);

    k_final<<<(GG * DD + TB - 1) / TB, TB>>>(P[24], P[25], P[26], P[27], out);
}